// round 16
// baseline (speedup 1.0000x reference)
#include <cuda_runtime.h>
#include <cstdint>

// QuantumConv1d — fused kernel with intra-CTA cp.async pipeline.
// Per CTA (128-l chunk = two 64-l halves):
//   stage A + Q-fold -> sync -> issue cp.async(B) -> conv A -> sync ->
//   store A (B's loads complete underneath) -> wait+sync -> conv B -> sync -> store B.
// Store phase per half: 16 warps, lane = (rr,ff): 2 o-rows x 16 float4 per iter,
// each lane reads the 4 ez rows its float4 spans. __stcs streaming stores.

#define C_IN     80
#define L_IN     3000
#define OUT_CH   512
#define KW       3
#define CHUNK    128
#define HALF     64
#define THREADS  512
#define XS       67        // padded row stride

__device__ __forceinline__ void cp_async4(uint32_t dst_smem, const void* src) {
    asm volatile("cp.async.ca.shared.global [%0], [%1], 4;\n"
                 :: "r"(dst_smem), "l"(src));
}

__global__ __launch_bounds__(THREADS, 3)
void qconv_fused(const float* __restrict__ x,
                 const float* __restrict__ W_pre,
                 const float* __restrict__ b_pre,
                 const float* __restrict__ W_post,
                 const float* __restrict__ b_post,
                 const float* __restrict__ qw,
                 float* __restrict__ out)
{
    __shared__ float x_s[2][C_IN][XS];      // 42.9 KB
    __shared__ float w_s[C_IN * 12];        // 3.75 KB
    __shared__ float ez_s[2][HALF][4];      // 2 KB
    __shared__ float Q_s[4][16];
    __shared__ float bpre_s[4];

    const int tid = threadIdx.x;
    const int b   = blockIdx.y;
    const int l0  = blockIdx.x * CHUNK;
    const float* xb = x + (size_t)b * C_IN * L_IN;

    // ======== Phase 0: Q fold (warp 0, lane-distributed) || stage half A ========
    if (tid < 32) {
        const int lane = tid;
        const int jm   = lane >> 2;
        const int k    = lane & 3;
        float ar0 = (jm == k) ? 1.f : 0.f, ai0 = 0.f;
        float ar1 = 0.f,                   ai1 = 0.f;

        {
            float phi = __ldg(qw + 0), th = __ldg(qw + 1), om = __ldg(qw + 2);
            float sh, ch; __sincosf(0.5f * th, &sh, &ch);
            float a = 0.5f * (phi + om), d = 0.5f * (phi - om);
            float sa, ca, sd, cd;
            __sincosf(a, &sa, &ca); __sincosf(d, &sd, &cd);
            float u00r =  ch * ca, u00i = -ch * sa;
            float u01r = -sh * cd, u01i = -sh * sd;
            float u10r =  sh * cd, u10i = -sh * sd;
            float u11r =  ch * ca, u11i =  ch * sa;
            float n0r = u00r*ar0 - u00i*ai0 + u01r*ar1 - u01i*ai1;
            float n0i = u00r*ai0 + u00i*ar0 + u01r*ai1 + u01i*ar1;
            float n1r = u10r*ar0 - u10i*ai0 + u11r*ar1 - u11i*ai1;
            float n1i = u10r*ai0 + u10i*ar0 + u11r*ai1 + u11i*ar1;
            ar0 = n0r; ai0 = n0i; ar1 = n1r; ai1 = n1i;
        }
        #pragma unroll
        for (int w = 1; w < 4; w++) {
            float phi = __ldg(qw + w * 3 + 0), th = __ldg(qw + w * 3 + 1), om = __ldg(qw + w * 3 + 2);
            float sh, ch; __sincosf(0.5f * th, &sh, &ch);
            float a = 0.5f * (phi + om), d = 0.5f * (phi - om);
            float sa, ca, sd, cd;
            __sincosf(a, &sa, &ca); __sincosf(d, &sd, &cd);
            float u00r =  ch * ca, u00i = -ch * sa;
            float u01r = -sh * cd, u01i = -sh * sd;
            float u10r =  sh * cd, u10i = -sh * sd;
            float u11r =  ch * ca, u11i =  ch * sa;
            const int s = 8 >> w;
            float p0r = __shfl_xor_sync(0xffffffffu, ar0, 4 * s);
            float p0i = __shfl_xor_sync(0xffffffffu, ai0, 4 * s);
            float p1r = __shfl_xor_sync(0xffffffffu, ar1, 4 * s);
            float p1i = __shfl_xor_sync(0xffffffffu, ai1, 4 * s);
            float n0r, n0i, n1r, n1i;
            if ((jm & s) == 0) {
                n0r = u00r*ar0 - u00i*ai0 + u01r*p0r - u01i*p0i;
                n0i = u00r*ai0 + u00i*ar0 + u01r*p0i + u01i*p0r;
                n1r = u00r*ar1 - u00i*ai1 + u01r*p1r - u01i*p1i;
                n1i = u00r*ai1 + u00i*ar1 + u01r*p1i + u01i*p1r;
            } else {
                n0r = u10r*p0r - u10i*p0i + u11r*ar0 - u11i*ai0;
                n0i = u10r*p0i + u10i*p0r + u11r*ai0 + u11i*ar0;
                n1r = u10r*p1r - u10i*p1i + u11r*ar1 - u11i*ai1;
                n1i = u10r*p1i + u10i*p1r + u11r*ai1 + u11i*ar1;
            }
            ar0 = n0r; ai0 = n0i; ar1 = n1r; ai1 = n1i;
        }
        int f0 = jm;
        if (f0 & 4) f0 ^= 2;
        if (f0 & 2) f0 ^= 1;
        int f1 = (jm + 8) ^ 4;
        if (f1 & 4) f1 ^= 2;
        if (f1 & 2) f1 ^= 1;

        float Qa[4][4];
        #pragma unroll
        for (int m = 0; m < 4; m++) {
            const int src = (lane & ~3) | m;
            float a0rm = __shfl_sync(0xffffffffu, ar0, src);
            float a0im = __shfl_sync(0xffffffffu, ai0, src);
            float a1rm = __shfl_sync(0xffffffffu, ar1, src);
            float a1im = __shfl_sync(0xffffffffu, ai1, src);
            float p0 = ar0 * a0rm + ai0 * a0im;
            float p1 = ar1 * a1rm + ai1 * a1im;
            Qa[0][m] = ((f0 & 8) ? -p0 : p0) + ((f1 & 8) ? -p1 : p1);
            Qa[1][m] = ((f0 & 4) ? -p0 : p0) + ((f1 & 4) ? -p1 : p1);
            Qa[2][m] = ((f0 & 2) ? -p0 : p0) + ((f1 & 2) ? -p1 : p1);
            Qa[3][m] = ((f0 & 1) ? -p0 : p0) + ((f1 & 1) ? -p1 : p1);
        }
        #pragma unroll
        for (int q = 0; q < 4; q++)
            #pragma unroll
            for (int m = 0; m < 4; m++) {
                float v = Qa[q][m];
                v += __shfl_xor_sync(0xffffffffu, v, 4);
                v += __shfl_xor_sync(0xffffffffu, v, 8);
                v += __shfl_xor_sync(0xffffffffu, v, 16);
                Qa[q][m] = v;
            }
        if (lane < 4) {
            #pragma unroll
            for (int q = 0; q < 4; q++)
                #pragma unroll
                for (int m = 0; m < 4; m++)
                    Q_s[q][lane * 4 + m] = Qa[q][m];
            bpre_s[lane] = b_pre[lane];
        }
    } else {
        const int t = tid - 32;
        for (int i = t; i < C_IN * 12; i += THREADS - 32) {
            int c = i / 12; int r = i - c * 12; int k = r >> 2; int q = r & 3;
            w_s[i] = W_pre[q * (C_IN * KW) + c * KW + k];
        }
        for (int i = t; i < C_IN * 16; i += THREADS - 32) {
            int c  = i >> 4;
            int qq = i & 15;
            int l  = l0 + qq * 4;
            float4 vv;
            if (l + 3 < L_IN) {
                vv = *(const float4*)(xb + (size_t)c * L_IN + l);
            } else {
                vv.x = (l + 0 < L_IN) ? xb[(size_t)c * L_IN + l + 0] : 0.f;
                vv.y = (l + 1 < L_IN) ? xb[(size_t)c * L_IN + l + 1] : 0.f;
                vv.z = (l + 2 < L_IN) ? xb[(size_t)c * L_IN + l + 2] : 0.f;
                vv.w = (l + 3 < L_IN) ? xb[(size_t)c * L_IN + l + 3] : 0.f;
            }
            x_s[0][c][1 + qq * 4] = vv.x;
            x_s[0][c][2 + qq * 4] = vv.y;
            x_s[0][c][3 + qq * 4] = vv.z;
            x_s[0][c][4 + qq * 4] = vv.w;
        }
        for (int c = t; c < C_IN; c += THREADS - 32) {
            int ll = l0 - 1;
            x_s[0][c][0]  = (ll >= 0) ? xb[(size_t)c * L_IN + ll] : 0.f;
            int lr = l0 + HALF;
            x_s[0][c][65] = (lr < L_IN) ? xb[(size_t)c * L_IN + lr] : 0.f;
        }
    }
    __syncthreads();

    // ======== issue cp.async for half B; completes under store A ========
    {
        const int baseB = l0 + HALF - 1;            // l for j=0 (>= 63)
        for (int i = tid; i < C_IN * 66; i += THREADS) {
            int c = i / 66;
            int j = i - c * 66;
            int l = baseB + j;
            if (l < L_IN) {
                uint32_t dst = (uint32_t)__cvta_generic_to_shared(&x_s[1][c][j]);
                cp_async4(dst, xb + (size_t)c * L_IN + l);
            } else {
                x_s[1][c][j] = 0.f;
            }
        }
        asm volatile("cp.async.commit_group;\n" ::: "memory");
    }

    const int pos = tid >> 3;                   // 0..63
    const int grp = tid & 7;                    // 0..7
    const int wrp = tid >> 5;                   // 0..15
    const int rr  = (tid & 31) >> 4;            // 0..1
    const int ff  = tid & 15;                   // 0..15
    float* outb = out + (size_t)b * OUT_CH * L_IN;

    #pragma unroll
    for (int h = 0; h < 2; h++) {
        if (h == 1) {
            asm volatile("cp.async.wait_group 0;\n" ::: "memory");
            __syncthreads();
        }
        // ---- conv: 8-way channel split + shfl reduce + quadratic form ----
        {
            float v0 = 0.f, v1 = 0.f, v2 = 0.f, v3 = 0.f;
            #pragma unroll
            for (int ci = 0; ci < 10; ci++) {
                const int c = grp + ci * 8;
                float xa  = x_s[h][c][pos];
                float xb1 = x_s[h][c][pos + 1];
                float xc  = x_s[h][c][pos + 2];
                const float4* wr = (const float4*)&w_s[c * 12];
                float4 w0 = wr[0], w1 = wr[1], w2 = wr[2];
                v0 += w0.x * xa + w1.x * xb1 + w2.x * xc;
                v1 += w0.y * xa + w1.y * xb1 + w2.y * xc;
                v2 += w0.z * xa + w1.z * xb1 + w2.z * xc;
                v3 += w0.w * xa + w1.w * xb1 + w2.w * xc;
            }
            v0 += __shfl_xor_sync(0xffffffffu, v0, 1);
            v1 += __shfl_xor_sync(0xffffffffu, v1, 1);
            v2 += __shfl_xor_sync(0xffffffffu, v2, 1);
            v3 += __shfl_xor_sync(0xffffffffu, v3, 1);
            v0 += __shfl_xor_sync(0xffffffffu, v0, 2);
            v1 += __shfl_xor_sync(0xffffffffu, v1, 2);
            v2 += __shfl_xor_sync(0xffffffffu, v2, 2);
            v3 += __shfl_xor_sync(0xffffffffu, v3, 2);
            v0 += __shfl_xor_sync(0xffffffffu, v0, 4);
            v1 += __shfl_xor_sync(0xffffffffu, v1, 4);
            v2 += __shfl_xor_sync(0xffffffffu, v2, 4);
            v3 += __shfl_xor_sync(0xffffffffu, v3, 4);

            v0 += bpre_s[0]; v1 += bpre_s[1]; v2 += bpre_s[2]; v3 += bpre_s[3];

            if (grp < 4) {
                const float inv = __frcp_rn(v0 * v0 + v1 * v1 + v2 * v2 + v3 * v3);
                const float* Qr = &Q_s[grp][0];
                float s;
                s  = v0 * (Qr[0]  * v0 + Qr[1]  * v1 + Qr[2]  * v2 + Qr[3]  * v3);
                s += v1 * (Qr[4]  * v0 + Qr[5]  * v1 + Qr[6]  * v2 + Qr[7]  * v3);
                s += v2 * (Qr[8]  * v0 + Qr[9]  * v1 + Qr[10] * v2 + Qr[11] * v3);
                s += v3 * (Qr[12] * v0 + Qr[13] * v1 + Qr[14] * v2 + Qr[15] * v3);
                ez_s[h][pos][grp] = s * inv;
            }
        }
        __syncthreads();

        // ---- store: lane (rr,ff) covers 2 o-rows x 4 l positions (ez rows 4ff..4ff+3)
        {
            const int l4 = l0 + h * HALF + ff * 4;
            if (l4 < L_IN) {                     // L_IN % 4 == 0: no straddle
                const float4* ez4 = (const float4*)&ez_s[h][0][0];
                const float4 e0 = ez4[ff * 4 + 0];
                const float4 e1 = ez4[ff * 4 + 1];
                const float4 e2 = ez4[ff * 4 + 2];
                const float4 e3 = ez4[ff * 4 + 3];
                #pragma unroll 16
                for (int it = 0; it < 16; it++) {
                    const int o = it * 32 + wrp * 2 + rr;
                    const float4 wp = __ldg((const float4*)(W_post + o * 4));
                    const float  bp = __ldg(b_post + o);
                    float4 r4;
                    r4.x = fmaf(wp.x, e0.x, fmaf(wp.y, e0.y, fmaf(wp.z, e0.z, fmaf(wp.w, e0.w, bp))));
                    r4.y = fmaf(wp.x, e1.x, fmaf(wp.y, e1.y, fmaf(wp.z, e1.z, fmaf(wp.w, e1.w, bp))));
                    r4.z = fmaf(wp.x, e2.x, fmaf(wp.y, e2.y, fmaf(wp.z, e2.z, fmaf(wp.w, e2.w, bp))));
                    r4.w = fmaf(wp.x, e3.x, fmaf(wp.y, e3.y, fmaf(wp.z, e3.z, fmaf(wp.w, e3.w, bp))));
                    __stcs((float4*)(outb + (size_t)o * L_IN + l4), r4);
                }
            }
        }
        __syncthreads();
    }
}

extern "C" void kernel_launch(void* const* d_in, const int* in_sizes, int n_in,
                              void* d_out, int out_size)
{
    const float* x      = (const float*)d_in[0];
    const float* W_pre  = (const float*)d_in[1];
    const float* b_pre  = (const float*)d_in[2];
    const float* W_post = (const float*)d_in[3];
    const float* b_post = (const float*)d_in[4];
    const float* qw     = (const float*)d_in[5];
    float* out = (float*)d_out;

    const int B = in_sizes[0] / (C_IN * L_IN);              // 32
    const int n_chunks = (L_IN + CHUNK - 1) / CHUNK;        // 24

    dim3 grid(n_chunks, B);
    qconv_fused<<<grid, THREADS>>>(x, W_pre, b_pre, W_post, b_post, qw, out);
}